// round 9
// baseline (speedup 1.0000x reference)
#include <cuda_runtime.h>
#include <cuda_fp16.h>
#include <cstdint>

// ============================ problem sizes ============================
#define BB    32
#define CIN   256
#define COUT  512
#define HWSZ  4096                  // 64*64
#define KTOT  256
#define NPIX  131072.0f             // B*H*W per channel

// ============================ device scratch ============================
__device__ __align__(128) float  g_noise[CIN * HWSZ];            // 4 MB
__device__ __align__(128) __half g_w[COUT * KTOT];               // 256 KB  [o][c]
__device__ __align__(128) __half g_y[(size_t)BB * COUT * HWSZ];  // 134 MB
__device__ float g_sum[COUT];
__device__ float g_sq[COUT];

// ============================ helpers ============================
__device__ __forceinline__ uint32_t smem_u32(const void* p) {
    uint32_t a;
    asm("{ .reg .u64 t; cvta.to.shared.u64 t, %1; cvt.u32.u64 %0, t; }" : "=r"(a) : "l"(p));
    return a;
}
__device__ __forceinline__ void ldsm_x4(uint32_t& r0, uint32_t& r1, uint32_t& r2, uint32_t& r3,
                                        uint32_t addr) {
    asm volatile("ldmatrix.sync.aligned.m8n8.x4.shared.b16 {%0,%1,%2,%3}, [%4];"
                 : "=r"(r0), "=r"(r1), "=r"(r2), "=r"(r3) : "r"(addr));
}
__device__ __forceinline__ void ldsm_x4_t(uint32_t& r0, uint32_t& r1, uint32_t& r2, uint32_t& r3,
                                          uint32_t addr) {
    asm volatile("ldmatrix.sync.aligned.m8n8.x4.trans.shared.b16 {%0,%1,%2,%3}, [%4];"
                 : "=r"(r0), "=r"(r1), "=r"(r2), "=r"(r3) : "r"(addr));
}
__device__ __forceinline__ void mma16816(float* d, const uint32_t* a, uint32_t b0, uint32_t b1) {
    asm volatile("mma.sync.aligned.m16n8k16.row.col.f32.f16.f16.f32 "
                 "{%0,%1,%2,%3}, {%4,%5,%6,%7}, {%8,%9}, {%0,%1,%2,%3};"
                 : "+f"(d[0]), "+f"(d[1]), "+f"(d[2]), "+f"(d[3])
                 : "r"(a[0]), "r"(a[1]), "r"(a[2]), "r"(a[3]), "r"(b0), "r"(b1));
}
__device__ __forceinline__ void cp_async16(uint32_t smem_dst, const void* gsrc) {
    asm volatile("cp.async.cg.shared.global [%0], [%1], 16;"
                 :: "r"(smem_dst), "l"(gsrc) : "memory");
}
#define CP_COMMIT() asm volatile("cp.async.commit_group;" ::: "memory")
#define CP_WAIT0()  asm volatile("cp.async.wait_group 0;" ::: "memory")

// ============================ kernel 0: init ============================
struct LCGTab { unsigned A[21]; unsigned C[21]; };
__host__ __device__ constexpr LCGTab make_tab() {
    LCGTab t{};
    unsigned a = 65539u, c = 1u;
    for (int j = 0; j < 21; j++) {
        t.A[j] = a; t.C[j] = c;
        unsigned c2 = a * c + c;
        a = a * a; c = c2;
    }
    return t;
}
__global__ void k_init(const float* __restrict__ w) {
    constexpr LCGTab T = make_tab();
    int i = blockIdx.x * blockDim.x + threadIdx.x;   // 0 .. 1048575
    unsigned n = (unsigned)i + 1u;
    unsigned rA = 1u, rC = 0u;
    #pragma unroll
    for (int j = 0; j < 21; j++) {
        if ((n >> j) & 1u) { rA = T.A[j] * rA; rC = T.A[j] * rC + T.C[j]; }
    }
    unsigned seed = rA * 12345u + rC;
    g_noise[i] = (float)seed * (float)(0.1 / 4294967295.0);

    if (i < COUT * KTOT) g_w[i] = __float2half_rn(w[i]);
    if (i < COUT) { g_sum[i] = 0.0f; g_sq[i] = 0.0f; }
}

// ============================ kernel 1: fused GEMM v4 (2 CTAs/SM, cp.async B) ============================
// CTA: 128 m-pixels x all 512 out-channels. A = relu(x+noise) fp16, full-K in smem
// (x read from DRAM once). B double-buffered via cp.async: B(kc+1) DMA overlaps
// phase-kc MMA. Epilogue: one-pass smem transpose through the 36.9KB B region.
#define SMA_OFF    0                       // [256 k][136 m] half = 69632 B
#define SMB_OFF    69632                   // 2 x [128 n][72 k] half = 36864 B
#define STAT_OFF   106496                  // 256 floats = 1024 B
#define SM_TOTAL   107520
#define SMA_STRIDE 136
#define SMB_STRIDE 72
#define SMB_BUF_B  18432                   // bytes per B buffer

__global__ void __launch_bounds__(256, 2) k_gemm(const float* __restrict__ x) {
    extern __shared__ char smem[];
    __half* smA = (__half*)(smem + SMA_OFF);
    float*  sums = (float*)(smem + STAT_OFF);
    float*  sqs  = sums + 128;
    uint32_t smA_u = smem_u32(smA);
    uint32_t smB_u = smem_u32(smem + SMB_OFF);

    int tid = threadIdx.x, warp = tid >> 5, lane = tid & 31;
    int mtile = blockIdx.x;            // 0..1023
    int b   = mtile >> 5;
    int hw0 = (mtile & 31) << 7;       // 128-pixel contiguous hw slab

    int mw = (warp >> 2) * 64;         // warp m offset
    int nw = (warp & 3) * 32;          // warp n offset within 128-n tile
    int cl = warp * 8;                 // channels staged per warp per chunk
    int brow = tid & 127, bpart = tid >> 7;
    uint32_t bdst_lane = smB_u + (uint32_t)(brow * SMB_STRIDE + bpart * 32) * 2u;

    float acc[16][4];
    #pragma unroll
    for (int i = 0; i < 16; i++)
        #pragma unroll
        for (int j = 0; j < 4; j++) acc[i][j] = 0.0f;

    uint32_t aaddr = smA_u + (uint32_t)(((lane & 7) + ((lane >> 4) << 3)) * SMA_STRIDE
                                        + mw + ((lane >> 3) & 1) * 8) * 2u;
    uint32_t blane = smB_u + (uint32_t)((nw + (lane & 7) + ((lane >> 4) << 3)) * SMB_STRIDE
                                        + ((lane >> 3) & 1) * 8) * 2u;
    int g = lane >> 2, t = lane & 3;

    for (int nt = 0; nt < 4; nt++) {
        // issue B(nt, 0) into buf 0
        {
            const __half* src = g_w + (size_t)(nt * 128 + brow) * KTOT + bpart * 32;
            #pragma unroll
            for (int i = 0; i < 4; i++)
                cp_async16(bdst_lane + i * 16, src + i * 8);
            CP_COMMIT();
        }

        for (int kc = 0; kc < 4; kc++) {
            CP_WAIT0();
            __syncthreads();                     // B(kc) visible to all; prev MMA done
            // issue B(kc+1) into the other buffer (DMA overlaps this phase's MMA)
            if (kc < 3) {
                uint32_t dst = bdst_lane + (uint32_t)(((kc + 1) & 1) * SMB_BUF_B);
                const __half* src = g_w + (size_t)(nt * 128 + brow) * KTOT
                                    + (kc + 1) * 64 + bpart * 32;
                #pragma unroll
                for (int i = 0; i < 4; i++)
                    cp_async16(dst + i * 16, src + i * 8);
                CP_COMMIT();
            }
            // stage A chunk kc (first n-tile only; A stays resident after)
            if (nt == 0) {
                #pragma unroll
                for (int r = 0; r < 8; r++) {
                    int c = kc * 64 + cl + r;
                    float4 xv = *(const float4*)(x + ((size_t)(b * CIN + c)) * HWSZ + hw0 + lane * 4);
                    float4 nv = *(const float4*)(g_noise + (size_t)c * HWSZ + hw0 + lane * 4);
                    __half2 h01 = __floats2half2_rn(fmaxf(xv.x + nv.x, 0.0f), fmaxf(xv.y + nv.y, 0.0f));
                    __half2 h23 = __floats2half2_rn(fmaxf(xv.z + nv.z, 0.0f), fmaxf(xv.w + nv.w, 0.0f));
                    uint2 pack;
                    pack.x = *(uint32_t*)&h01;
                    pack.y = *(uint32_t*)&h23;
                    *(uint2*)(smA + c * SMA_STRIDE + lane * 4) = pack;
                }
                __syncthreads();                 // A chunk kc visible before MMA
            }

            uint32_t abase = aaddr + (uint32_t)(kc * 64 * SMA_STRIDE) * 2u;
            uint32_t bbase = blane + (uint32_t)((kc & 1) * SMB_BUF_B);
            #pragma unroll
            for (int ks = 0; ks < 4; ks++) {
                uint32_t afr[4][4];
                #pragma unroll
                for (int mi = 0; mi < 4; mi++)
                    ldsm_x4_t(afr[mi][0], afr[mi][1], afr[mi][2], afr[mi][3],
                              abase + (uint32_t)(ks * 16 * SMA_STRIDE + mi * 16) * 2u);
                uint32_t bfr[2][4];
                #pragma unroll
                for (int nip = 0; nip < 2; nip++)
                    ldsm_x4(bfr[nip][0], bfr[nip][1], bfr[nip][2], bfr[nip][3],
                            bbase + (uint32_t)(nip * 16 * SMB_STRIDE + ks * 16) * 2u);
                #pragma unroll
                for (int mi = 0; mi < 4; mi++)
                    #pragma unroll
                    for (int ni = 0; ni < 4; ni++)
                        mma16816(acc[mi * 4 + ni], afr[mi],
                                 bfr[ni >> 1][(ni & 1) * 2], bfr[ni >> 1][(ni & 1) * 2 + 1]);
            }
        }
        __syncthreads();                         // all MMA reads of B region done

        // ---- epilogue for ntile nt: BN stats + one-pass fp16 y (smY = B region) ----
        if (tid < 128) { sums[tid] = 0.0f; sqs[tid] = 0.0f; }

        float lsum[8], lsq[8];
        #pragma unroll
        for (int j = 0; j < 8; j++) { lsum[j] = 0.0f; lsq[j] = 0.0f; }

        __half* smY = (__half*)(smem + SMB_OFF);   // [128 n][136 m] = 34816 B
        #pragma unroll
        for (int mi = 0; mi < 4; mi++)
            #pragma unroll
            for (int ni = 0; ni < 4; ni++) {
                float c0 = acc[mi * 4 + ni][0], c1 = acc[mi * 4 + ni][1];
                float c2 = acc[mi * 4 + ni][2], c3 = acc[mi * 4 + ni][3];
                int m0 = mw + mi * 16 + g;
                int n0 = nw + ni * 8 + t * 2;
                smY[n0 * SMA_STRIDE + m0]           = __float2half_rn(c0);
                smY[(n0 + 1) * SMA_STRIDE + m0]     = __float2half_rn(c1);
                smY[n0 * SMA_STRIDE + m0 + 8]       = __float2half_rn(c2);
                smY[(n0 + 1) * SMA_STRIDE + m0 + 8] = __float2half_rn(c3);
                int j0 = ni * 2;
                lsum[j0]     += c0 + c2;  lsq[j0]     += c0 * c0 + c2 * c2;
                lsum[j0 + 1] += c1 + c3;  lsq[j0 + 1] += c1 * c1 + c3 * c3;
                acc[mi * 4 + ni][0] = 0.0f; acc[mi * 4 + ni][1] = 0.0f;
                acc[mi * 4 + ni][2] = 0.0f; acc[mi * 4 + ni][3] = 0.0f;
            }
        #pragma unroll
        for (int j = 0; j < 8; j++) {
            #pragma unroll
            for (int off = 4; off <= 16; off <<= 1) {
                lsum[j] += __shfl_xor_sync(0xFFFFFFFFu, lsum[j], off);
                lsq[j]  += __shfl_xor_sync(0xFFFFFFFFu, lsq[j], off);
            }
        }
        __syncthreads();                          // smY complete; stat zero visible
        if (g == 0) {
            #pragma unroll
            for (int j = 0; j < 8; j++) {
                int n = nw + (j >> 1) * 8 + t * 2 + (j & 1);
                atomicAdd(&sums[n], lsum[j]);
                atomicAdd(&sqs[n],  lsq[j]);
            }
        }
        // coalesced y store: each warp 16 n-rows, 256B per row
        #pragma unroll
        for (int i = 0; i < 16; i++) {
            int n = warp * 16 + i;
            uint2 v = *(uint2*)(smY + n * SMA_STRIDE + lane * 4);
            *(uint2*)(g_y + ((size_t)(b * COUT + nt * 128 + n)) * HWSZ + hw0 + lane * 4) = v;
        }
        if (tid < 128) {
            atomicAdd(&g_sum[nt * 128 + tid], sums[tid]);
            atomicAdd(&g_sq[nt * 128 + tid],  sqs[tid]);
        }
        __syncthreads();                          // smY reads done before next nt's cp.async
    }
}

// ============================ kernel 2: BN normalize ============================
// Reverse traversal: read y starting from its most-recently-written end so the
// ~126MB L2 still holds it (y = 134MB). 32B/thread.
__global__ void k_norm(float* __restrict__ out,
                       const float* __restrict__ gamma,
                       const float* __restrict__ beta) {
    size_t lin  = (size_t)blockIdx.x * blockDim.x + threadIdx.x;   // 8,388,608 threads
    size_t idx8 = (8388608u - 1u) - lin;                           // 8-elem group, reversed
    int o = (int)((idx8 >> 9) & (COUT - 1));                       // 512 groups per (b,o) slab
    float mean = g_sum[o] * (1.0f / NPIX);
    float var  = g_sq[o]  * (1.0f / NPIX) - mean * mean;
    float inv  = rsqrtf(var + 1e-5f);
    float ga = gamma[o] * inv;
    float be = beta[o] - mean * ga;
    uint4 p = __ldcs((const uint4*)(g_y + idx8 * 8));
    float4 o0, o1;
    {
        float2 f0 = __half22float2(*(__half2*)&p.x);
        float2 f1 = __half22float2(*(__half2*)&p.y);
        o0.x = f0.x * ga + be; o0.y = f0.y * ga + be;
        o0.z = f1.x * ga + be; o0.w = f1.y * ga + be;
    }
    {
        float2 f2 = __half22float2(*(__half2*)&p.z);
        float2 f3 = __half22float2(*(__half2*)&p.w);
        o1.x = f2.x * ga + be; o1.y = f2.y * ga + be;
        o1.z = f3.x * ga + be; o1.w = f3.y * ga + be;
    }
    __stcs(((float4*)out) + idx8 * 2,     o0);
    __stcs(((float4*)out) + idx8 * 2 + 1, o1);
}

// ============================ launcher ============================
extern "C" void kernel_launch(void* const* d_in, const int* in_sizes, int n_in,
                              void* d_out, int out_size) {
    const float* x     = (const float*)d_in[0];
    const float* w     = (const float*)d_in[1];
    // d_in[2] = conv_b: exactly cancelled by BatchNorm mean subtraction.
    const float* gamma = (const float*)d_in[3];
    const float* beta  = (const float*)d_in[4];
    float* out = (float*)d_out;

    cudaFuncSetAttribute(k_gemm, cudaFuncAttributeMaxDynamicSharedMemorySize, SM_TOTAL);

    k_init<<<4096, 256>>>(w);                 // noise table + fp16 W + zero stats
    k_gemm<<<1024, 256, SM_TOTAL>>>(x);       // fused noise+relu+GEMM+BN-stats, y fp16
    k_norm<<<32768, 256>>>(out, gamma, beta); // finalize BN -> fp32 out (reversed)
}